// round 3
// baseline (speedup 1.0000x reference)
#include <cuda_runtime.h>

#define Bn   16
#define CIN  64
#define COUT 64
#define Hn   130
#define Wn   130
#define HOn  128
#define WOn  128
#define Gn   8
#define CPGn 8
#define OFFC 144   // G*2*K*K = 8*2*9
#define HWo  16384 // 128*128
#define HWi  16900 // 130*130

// Intermediate feature map t = conv3x3(x, w1) + b1  : [16,64,128,128]
__device__ float g_t[(size_t)Bn * CIN * HOn * WOn];

// ---------------------------------------------------------------------------
// Kernel 1: 3x3 VALID conv, 64->64.  Tile 32x16 spatial x 16 out-ch per block.
// Each thread: 2 y-pixels x 16 out channels (32 accumulators).
// ---------------------------------------------------------------------------
__global__ __launch_bounds__(256) void conv3x3_kernel(
    const float* __restrict__ x, const float* __restrict__ w1,
    const float* __restrict__ b1)
{
    const int tx = threadIdx.x;            // 0..31
    const int ty = threadIdx.y;            // 0..7
    const int tid = ty * 32 + tx;
    const int tileX = blockIdx.x * 32;
    const int tileY = blockIdx.y * 16;
    const int b = blockIdx.z >> 2;
    const int coBase = (blockIdx.z & 3) * 16;

    __shared__ float s_in[18][36];   // (16+2) x (32+2), padded cols
    __shared__ float s_w[9][16];     // [k][co], co contiguous for float4

    float acc0[16], acc1[16];
#pragma unroll
    for (int i = 0; i < 16; ++i) { acc0[i] = 0.f; acc1[i] = 0.f; }

    for (int ci = 0; ci < CIN; ++ci) {
        const float* xp = x + ((size_t)(b * CIN + ci)) * HWi;
        // load 18x34 input tile (always in bounds: tileY+17<=129, tileX+33<=129)
        for (int e = tid; e < 18 * 34; e += 256) {
            int r = e / 34, c = e - r * 34;
            s_in[r][c] = xp[(tileY + r) * Wn + (tileX + c)];
        }
        if (tid < 144) {
            int k = tid >> 4, co = tid & 15;
            s_w[k][co] = w1[((size_t)(coBase + co) * CIN + ci) * 9 + k];
        }
        __syncthreads();

        float in[4][3];
#pragma unroll
        for (int r = 0; r < 4; ++r)
#pragma unroll
            for (int c = 0; c < 3; ++c)
                in[r][c] = s_in[ty * 2 + r][tx + c];

#pragma unroll
        for (int ky = 0; ky < 3; ++ky)
#pragma unroll
            for (int kx = 0; kx < 3; ++kx) {
                float i0 = in[ky][kx];
                float i1 = in[ky + 1][kx];
                const float4* w4 = (const float4*)s_w[ky * 3 + kx];
#pragma unroll
                for (int q = 0; q < 4; ++q) {
                    float4 w = w4[q];
                    acc0[q * 4 + 0] += i0 * w.x;
                    acc0[q * 4 + 1] += i0 * w.y;
                    acc0[q * 4 + 2] += i0 * w.z;
                    acc0[q * 4 + 3] += i0 * w.w;
                    acc1[q * 4 + 0] += i1 * w.x;
                    acc1[q * 4 + 1] += i1 * w.y;
                    acc1[q * 4 + 2] += i1 * w.z;
                    acc1[q * 4 + 3] += i1 * w.w;
                }
            }
        __syncthreads();
    }

    const int oy = tileY + ty * 2;
    const int ox = tileX + tx;
#pragma unroll
    for (int co = 0; co < 16; ++co) {
        float bb = b1[coBase + co];
        size_t base = ((size_t)(b * COUT + coBase + co)) * HWo;
        g_t[base + (size_t)oy * WOn + ox] = acc0[co] + bb;
        g_t[base + (size_t)(oy + 1) * WOn + ox] = acc1[co] + bb;
    }
}

// ---------------------------------------------------------------------------
// Kernel 2: 1x1 conv 64->144 (offset prediction). Writes straight into d_out
// off-section. Block: 256 pixels x 48 out-ch, thread = 1 pixel, 48 acc.
// ---------------------------------------------------------------------------
__global__ __launch_bounds__(256, 2) void conv1x1_kernel(
    const float* __restrict__ w2, const float* __restrict__ b2,
    float* __restrict__ off)
{
    __shared__ float s_w[64 * 48];      // [cin][co48]
    __shared__ float s_t[16][256];      // cin-chunk x pixels

    const int tid = threadIdx.x;
    const int coBase = blockIdx.y * 48;
    const int p0 = blockIdx.x * 256;
    const int b = p0 >> 14;
    const int hwBase = p0 & (HWo - 1);

    for (int e = tid; e < 64 * 48; e += 256) {
        int cin = e / 48, co = e - cin * 48;
        s_w[e] = w2[(size_t)(coBase + co) * CIN + cin];
    }

    float acc[48];
#pragma unroll
    for (int i = 0; i < 48; ++i) acc[i] = 0.f;

    for (int chunk = 0; chunk < 4; ++chunk) {
        __syncthreads();
#pragma unroll
        for (int r = 0; r < 16; ++r)
            s_t[r][tid] = g_t[((size_t)(b * CIN + chunk * 16 + r)) * HWo + hwBase + tid];
        __syncthreads();
#pragma unroll
        for (int r = 0; r < 16; ++r) {
            float tv = s_t[r][tid];
            const float4* w4 = (const float4*)(s_w + (chunk * 16 + r) * 48);
#pragma unroll
            for (int q = 0; q < 12; ++q) {
                float4 w = w4[q];
                acc[q * 4 + 0] += tv * w.x;
                acc[q * 4 + 1] += tv * w.y;
                acc[q * 4 + 2] += tv * w.z;
                acc[q * 4 + 3] += tv * w.w;
            }
        }
    }

    const int hw = hwBase + tid;
#pragma unroll
    for (int co = 0; co < 48; ++co)
        off[((size_t)(b * OFFC + coBase + co)) * HWo + hw] = acc[co] + b2[coBase + co];
}

// ---------------------------------------------------------------------------
// Kernel 3: deformable conv. Thread = 1 output pixel, all 64 out channels in
// registers. Per offset-group g: stage wd[:, g*8:(g+1)*8, :, :] in smem
// (layout [ij][co][c], c contiguous -> float4 pairs).
// ---------------------------------------------------------------------------
__global__ __launch_bounds__(256, 2) void deform_kernel(
    const float* __restrict__ x, const float* __restrict__ wd,
    const float* __restrict__ off, float* __restrict__ y)
{
    __shared__ float s_wd[9 * 64 * 8];

    const int tx = threadIdx.x;      // 0..31
    const int ty = threadIdx.y;      // 0..7
    const int tid = ty * 32 + tx;
    const int wo = blockIdx.x * 32 + tx;
    const int ho = blockIdx.y * 8 + ty;
    const int b = blockIdx.z;

    float acc[64];
#pragma unroll
    for (int i = 0; i < 64; ++i) acc[i] = 0.f;

    for (int g = 0; g < Gn; ++g) {
        __syncthreads();   // previous group's compute done before overwrite
        for (int e = tid; e < 4608; e += 256) {
            int c = e & 7;
            int co = (e >> 3) & 63;
            int ij = e >> 9;
            int i = ij / 3, j = ij - i * 3;
            s_wd[e] = wd[(((size_t)co * CIN + g * CPGn + c) * 3 + i) * 3 + j];
        }
        __syncthreads();

        const float* xg = x + ((size_t)(b * CIN + g * CPGn)) * HWi;

        for (int ij = 0; ij < 9; ++ij) {
            const int i = ij / 3, j = ij - i * 3;
            const int ch = (g * 9 + ij) * 2;
            const size_t obase = ((size_t)(b * OFFC + ch)) * HWo + ho * WOn + wo;
            float dy = off[obase];
            float dx = off[obase + HWo];

            float py = dy + (float)(ho + i);
            float px = dx + (float)(wo + j);
            float y0f = floorf(py), x0f = floorf(px);
            float ly = py - y0f, lx = px - x0f;
            int y0 = (int)y0f, x0 = (int)x0f;
            int y1 = y0 + 1, x1 = x0 + 1;

            float vy0 = (y0 >= 0 && y0 < Hn) ? 1.f : 0.f;
            float vy1 = (y1 >= 0 && y1 < Hn) ? 1.f : 0.f;
            float vx0 = (x0 >= 0 && x0 < Wn) ? 1.f : 0.f;
            float vx1 = (x1 >= 0 && x1 < Wn) ? 1.f : 0.f;

            float w00 = (1.f - ly) * (1.f - lx) * vy0 * vx0;
            float w01 = (1.f - ly) * lx * vy0 * vx1;
            float w10 = ly * (1.f - lx) * vy1 * vx0;
            float w11 = ly * lx * vy1 * vx1;

            int yc0 = min(max(y0, 0), Hn - 1), yc1 = min(max(y1, 0), Hn - 1);
            int xc0 = min(max(x0, 0), Wn - 1), xc1 = min(max(x1, 0), Wn - 1);
            int i00 = yc0 * Wn + xc0, i01 = yc0 * Wn + xc1;
            int i10 = yc1 * Wn + xc0, i11 = yc1 * Wn + xc1;

            float v[8];
#pragma unroll
            for (int c = 0; c < 8; ++c) {
                const float* p = xg + (size_t)c * HWi;
                v[c] = w00 * __ldg(p + i00) + w01 * __ldg(p + i01)
                     + w10 * __ldg(p + i10) + w11 * __ldg(p + i11);
            }

            const float4* wrow = (const float4*)(s_wd + ij * 512);
#pragma unroll
            for (int co = 0; co < 64; ++co) {
                float4 wa = wrow[co * 2];
                float4 wb = wrow[co * 2 + 1];
                acc[co] += v[0] * wa.x + v[1] * wa.y + v[2] * wa.z + v[3] * wa.w
                         + v[4] * wb.x + v[5] * wb.y + v[6] * wb.z + v[7] * wb.w;
            }
        }
    }

#pragma unroll
    for (int co = 0; co < 64; ++co)
        y[((size_t)(b * COUT + co)) * HWo + ho * WOn + wo] = acc[co];
}

// ---------------------------------------------------------------------------
extern "C" void kernel_launch(void* const* d_in, const int* in_sizes, int n_in,
                              void* d_out, int out_size)
{
    const float* x  = (const float*)d_in[0];
    const float* w1 = (const float*)d_in[1];
    const float* b1 = (const float*)d_in[2];
    const float* w2 = (const float*)d_in[3];
    const float* b2 = (const float*)d_in[4];
    const float* wd = (const float*)d_in[5];

    float* y   = (float*)d_out;
    float* off = y + (size_t)Bn * COUT * HOn * WOn;   // off is output #2

    // t = conv3x3(x) + b1
    conv3x3_kernel<<<dim3(4, 8, Bn * 4), dim3(32, 8)>>>(x, w1, b1);
    // off = conv1x1(t) + b2  (written directly to output)
    conv1x1_kernel<<<dim3((Bn * HWo) / 256, 3), 256>>>(w2, b2, off);
    // y = deform_conv(x, off, wd)
    deform_kernel<<<dim3(WOn / 32, HOn / 8, Bn), dim3(32, 8)>>>(x, wd, off, y);
}